// round 8
// baseline (speedup 1.0000x reference)
#include <cuda_runtime.h>
#include <cuda_bf16.h>

#define BB 4
#define NN 2048
#define PARAM_G 0.125f
#define VIRUS_DEATH 8e-05f
#define NCHUNK 64               // row-chunks for colsum partials

// Scratch (allocation-free rule: __device__ globals). All fully overwritten
// each replay -> no zeroing, no atomics, deterministic.
// Transposed layout: the 64 chunk-partials of column j are CONTIGUOUS.
__device__ float g_part2[(size_t)BB * NN * NCHUNK];  // [b][j][c], 8 MB
__device__ float g_faip2[BB * 128];                  // per-colsum-CTA fai scalars

// ---------------------------------------------------------------------------
// Kernel 1: colsum partials. g_part2[b][j][ch] = sum over 32 rows of chunk ch
// of mob[b][i][j] (diagonal zeroed). Thread = 4 columns (float4), 512 CTAs.
// Also emits one block-level fai scalar per CTA.
// ---------------------------------------------------------------------------
__global__ void __launch_bounds__(256) colsum_part_kernel(const float* __restrict__ mob) {
    const int t  = threadIdx.x;
    const int c4 = blockIdx.x * 256 + t;          // float4 column group
    const int j0 = c4 * 4;
    const int b  = blockIdx.z;
    const int ch = blockIdx.y;
    const int i0 = ch * (NN / NCHUNK);
    const float4* base = (const float4*)(mob + (size_t)b * NN * NN) + c4;
    float4 s = make_float4(0.f, 0.f, 0.f, 0.f);
#pragma unroll 8
    for (int i = i0; i < i0 + NN / NCHUNK; ++i) {
        float4 v = base[(size_t)i * (NN / 4)];
        if (i == j0)     v.x = 0.0f;
        if (i == j0 + 1) v.y = 0.0f;
        if (i == j0 + 2) v.z = 0.0f;
        if (i == j0 + 3) v.w = 0.0f;
        s.x += v.x; s.y += v.y; s.z += v.z; s.w += v.w;
    }
    // Transposed store: column-contiguous chunk axis
    float* dst = g_part2 + ((size_t)(b * NN) + j0) * NCHUNK + ch;
    dst[0]          = s.x;
    dst[NCHUNK]     = s.y;
    dst[2 * NCHUNK] = s.z;
    dst[3 * NCHUNK] = s.w;

    // block reduce -> fai scalar for this CTA
    float st = s.x + s.y + s.z + s.w;
#pragma unroll
    for (int o = 16; o; o >>= 1) st += __shfl_down_sync(0xFFFFFFFFu, st, o);
    __shared__ float sh[8];
    const int w = t >> 5, l = t & 31;
    if (l == 0) sh[w] = st;
    __syncthreads();
    if (t == 0) {
        float F = 0.0f;
#pragma unroll
        for (int k = 0; k < 8; ++k) F += sh[k];
        g_faip2[b * 128 + ch * 2 + blockIdx.x] = F;
    }
}

// ---------------------------------------------------------------------------
// Kernel 2: main streaming pass (proven R2/R5 loop body). One warp per row i.
// All pre-work (colsum fold, m = fai/tau) done BEFORE the loop with coalesced
// access; no post-loop passes. Fused lane-0 epilogue.
// Output: [Ht_SIR (B*N*6)] [arrive1 (B*N*4)] [arrive2 (B*N*N*2)]
// ---------------------------------------------------------------------------
__global__ void __launch_bounds__(256) main_kernel(
    const float* __restrict__ param_b, const float* __restrict__ contact,
    const float* __restrict__ mob, const float* __restrict__ SIR,
    const float* __restrict__ sps, const float* __restrict__ birth,
    const float* __restrict__ death, float* __restrict__ out)
{
    __shared__ float sS[NN], sI[NN], sR[NN];   // 24 KB
    __shared__ float shT[8];
    __shared__ float sh_m;

    const int b = blockIdx.y;
    const int t = threadIdx.x;
    const int wid  = t >> 5;
    const int lane = t & 31;
    const int i    = blockIdx.x * 8 + wid;

    // Stage SIR into SoA smem, accumulating tau on the fly
    const float4* sir4 = (const float4*)(SIR + (size_t)b * NN * 4);
    float taup = 0.0f;
#pragma unroll
    for (int j = t; j < NN; j += 256) {
        float4 s = sir4[j];
        sS[j] = s.x; sI[j] = s.y; sR[j] = s.z;
        taup += s.x + s.y + s.z;
    }
#pragma unroll
    for (int o = 16; o; o >>= 1) taup += __shfl_down_sync(0xFFFFFFFFu, taup, o);
    if (lane == 0) shT[wid] = taup;
    __syncthreads();

    // Warp 0: m = fai / tau  (fai: 128 scalars, one float4 per lane)
    if (wid == 0) {
        const float4 fv = ((const float4*)(g_faip2 + b * 128))[lane];
        float F = fv.x + fv.y + fv.z + fv.w;
#pragma unroll
        for (int o = 16; o; o >>= 1) F += __shfl_down_sync(0xFFFFFFFFu, F, o);
        if (lane == 0) {
            float T = 0.0f;
#pragma unroll
            for (int k = 0; k < 8; ++k) T += shT[k];
            sh_m = F / T;
        }
    }

    // Per-warp colsum fold: 64 contiguous chunk-partials -> one coalesced
    // 256B float2 load per warp.
    const float2 pv = ((const float2*)(g_part2 + ((size_t)(b * NN) + i) * NCHUNK))[lane];
    float acc = pv.x + pv.y;
#pragma unroll
    for (int o = 16; o; o >>= 1) acc += __shfl_down_sync(0xFFFFFFFFu, acc, o);
    const float rcs = 1.0f / __shfl_sync(0xFFFFFFFFu, acc, 0);

    __syncthreads();   // sh_m ready; smem SIR ready

    const float4* mobr = (const float4*)(mob + ((size_t)b * NN + i) * NN);
    const float4* spsr = (const float4*)(sps + ((size_t)b * NN + i) * NN);
    const float4* sS4  = (const float4*)sS;
    const float4* sI4  = (const float4*)sI;
    const float4* sR4  = (const float4*)sR;
    const size_t OFF2 = (size_t)BB * NN * 6 + (size_t)BB * NN * 4;
    float4* out2 = (float4*)(out + OFF2 + ((size_t)b * NN + i) * (size_t)NN * 2);

    float fS = 0.0f, fI = 0.0f, fR = 0.0f;

#pragma unroll 4
    for (int k = lane; k < NN / 4; k += 32) {
        float4 f  = mobr[k];
        float4 sp = spsr[k];
        const int j0 = k * 4;
        if (j0     == i) { f.x = 0.0f; sp.x = 0.0f; }
        if (j0 + 1 == i) { f.y = 0.0f; sp.y = 0.0f; }
        if (j0 + 2 == i) { f.z = 0.0f; sp.z = 0.0f; }
        if (j0 + 3 == i) { f.w = 0.0f; sp.w = 0.0f; }

        const float4 vS = sS4[k];
        const float4 vI = sI4[k];
        const float4 vR = sR4[k];

        fS += f.x * vS.x + f.y * vS.y + f.z * vS.z + f.w * vS.w;
        fI += f.x * vI.x + f.y * vI.y + f.z * vI.z + f.w * vI.w;
        fR += f.x * vR.x + f.y * vR.y + f.z * vR.z + f.w * vR.w;

        out2[2 * k]     = make_float4(sp.x, f.x * rcs, sp.y, f.y * rcs);
        out2[2 * k + 1] = make_float4(sp.z, f.z * rcs, sp.w, f.w * rcs);
    }

#pragma unroll
    for (int o = 16; o; o >>= 1) {
        fS += __shfl_down_sync(0xFFFFFFFFu, fS, o);
        fI += __shfl_down_sync(0xFFFFFFFFu, fI, o);
        fR += __shfl_down_sync(0xFFFFFFFFu, fR, o);
    }

    if (lane == 0) {
        const float m_b = sh_m;
        const float S = sS[i], I = sI[i], R = sR[i];
        const float Isum = SIR[((size_t)b * NN + i) * 4 + 3];
        const float pop = S + I + R;
        const float pb  = param_b[b * NN + i];
        const float ct  = contact[b * NN + i];
        const float dth = death[i];
        const float brt = birth[i];

        const float fluxS = m_b * rcs * fS;
        const float fluxI = m_b * rcs * fI;
        const float fluxR = m_b * rcs * fR;

        const float I_new  = S / pop * pb * ct * I;
        const float R_t    = R + PARAM_G * I - dth * R - m_b * R + fluxR;
        const float I_t    = I + I_new - dth * I - PARAM_G * I - VIRUS_DEATH * I - m_b * I + fluxI;
        const float S_t    = S - I_new - dth * S + brt * pop - m_b * S + fluxS;
        const float Isum_t = Isum + I_new;
        const float R0     = pb * ct / (dth + PARAM_G + VIRUS_DEATH + m_b);
        const float W      = pb * ct - dth - PARAM_G - VIRUS_DEATH;

        float* ht = out + (size_t)(b * NN + i) * 6;
        ht[0] = R0;  ht[1] = I_new; ht[2] = S_t;
        ht[3] = I_t; ht[4] = R_t;   ht[5] = Isum_t;

        float* a1 = out + (size_t)BB * NN * 6 + (size_t)(b * NN + i) * 4;
        a1[0] = W; a1[1] = m_b; a1[2] = I; a1[3] = pop;
    }
}

// ---------------------------------------------------------------------------
extern "C" void kernel_launch(void* const* d_in, const int* in_sizes, int n_in,
                              void* d_out, int out_size) {
    const float* param_b = (const float*)d_in[0];
    const float* contact = (const float*)d_in[1];
    const float* mob     = (const float*)d_in[2];
    const float* SIR     = (const float*)d_in[3];
    const float* sps     = (const float*)d_in[4];
    const float* birth   = (const float*)d_in[5];
    const float* death   = (const float*)d_in[6];
    float* out = (float*)d_out;

    colsum_part_kernel<<<dim3(NN / 1024, NCHUNK, BB), 256>>>(mob);
    main_kernel<<<dim3(NN / 8, BB), 256>>>(param_b, contact, mob, SIR, sps,
                                           birth, death, out);
}